// round 7
// baseline (speedup 1.0000x reference)
#include <cuda_runtime.h>
#include <cuda_fp16.h>
#include <cstdint>
#include <math.h>

#define BB 4
#define TTOT 4096
#define CC 2048
#define NH 32
#define HS 64
#define ROWS (BB*TTOT)
#define ELEMS ((size_t)ROWS*(size_t)CC)
#define NCHUNK 16
#define TCH (TTOT/NCHUNK)

typedef __half f16;

#define BM 128
#define BN 128
#define BKT 32
#define TILE_B (128*80)
#define STAGE_B (3*TILE_B)
#define NSTG 3
#define SMEM_B (NSTG*STAGE_B)
#define KTILES (CC/BKT)

// ---------------------------------------------------------------------------
// Scratch
// ---------------------------------------------------------------------------
__device__ f16 g_xr_h[ELEMS]; __device__ f16 g_xr_l[ELEMS];
__device__ f16 g_xk_h[ELEMS]; __device__ f16 g_xk_l[ELEMS];
__device__ f16 g_xv_h[ELEMS]; __device__ f16 g_xv_l[ELEMS];
__device__ f16 g_xg_h[ELEMS]; __device__ f16 g_xg_l[ELEMS];
__device__ f16 g_y_h[ELEMS];  __device__ f16 g_y_l[ELEMS];
__device__ float g_r[ELEMS];
__device__ float g_k[ELEMS];
__device__ float g_v[ELEMS];
__device__ float g_g[ELEMS];
__device__ f16 g_WrT[CC*CC];
__device__ f16 g_WkT[CC*CC];
__device__ f16 g_WvT[CC*CC];
__device__ f16 g_WgT[CC*CC];
__device__ f16 g_WoT[CC*CC];
__device__ float g_Sc[(size_t)NCHUNK*128*HS*HS];
__device__ float g_S0c[(size_t)NCHUNK*128*HS*HS];

// ---------------------------------------------------------------------------
// helpers
// ---------------------------------------------------------------------------
__device__ __forceinline__ uint32_t smem_u32(const void* p) {
    uint32_t a;
    asm("{ .reg .u64 t; cvta.to.shared.u64 t, %1; cvt.u32.u64 %0, t; }" : "=r"(a) : "l"(p));
    return a;
}
__device__ __forceinline__ void cpa16(uint32_t dst, const void* src) {
    asm volatile("cp.async.cg.shared.global [%0], [%1], 16;" :: "r"(dst), "l"(src));
}
__device__ __forceinline__ void cp_commit() {
    asm volatile("cp.async.commit_group;" ::: "memory");
}
template<int N> __device__ __forceinline__ void cp_wait() {
    asm volatile("cp.async.wait_group %0;" :: "n"(N) : "memory");
}
__device__ __forceinline__ void ldsm4(uint32_t (&r)[4], uint32_t addr) {
    asm volatile("ldmatrix.sync.aligned.m8n8.x4.shared.b16 {%0,%1,%2,%3}, [%4];"
                 : "=r"(r[0]), "=r"(r[1]), "=r"(r[2]), "=r"(r[3]) : "r"(addr));
}
__device__ __forceinline__ void mma_f16(float (&c)[4], const uint32_t (&a)[4],
                                        uint32_t b0, uint32_t b1) {
    asm volatile(
        "mma.sync.aligned.m16n8k16.row.col.f32.f16.f16.f32 "
        "{%0,%1,%2,%3}, {%4,%5,%6,%7}, {%8,%9}, {%0,%1,%2,%3};"
        : "+f"(c[0]), "+f"(c[1]), "+f"(c[2]), "+f"(c[3])
        : "r"(a[0]), "r"(a[1]), "r"(a[2]), "r"(a[3]), "r"(b0), "r"(b1));
}
__device__ __forceinline__ void split_f16(float x, f16& h, f16& l) {
    h = __float2half_rn(x);
    l = __float2half_rn(x - __half2float(h));
}

// ---------------------------------------------------------------------------
// 1) Token-shift mixing -> fp16 hi/lo planes
// ---------------------------------------------------------------------------
__global__ void mix_kernel(const float* __restrict__ x,
                           const float* __restrict__ tmk, const float* __restrict__ tmv,
                           const float* __restrict__ tmr, const float* __restrict__ tmg,
                           f16* __restrict__ xkh, f16* __restrict__ xkl,
                           f16* __restrict__ xvh, f16* __restrict__ xvl,
                           f16* __restrict__ xrh, f16* __restrict__ xrl,
                           f16* __restrict__ xgh, f16* __restrict__ xgl) {
    size_t idx = (size_t)blockIdx.x * blockDim.x + threadIdx.x;
    if (idx >= ELEMS) return;
    int c = (int)(idx % CC);
    int t = (int)((idx / CC) % TTOT);
    float xc = x[idx];
    float xp = (t == 0) ? 0.0f : x[idx - CC];
    float mk = tmk[c], mv = tmv[c], mr = tmr[c], mg = tmg[c];
    float vk = xc * mk + xp * (1.0f - mk);
    float vv = xc * mv + xp * (1.0f - mv);
    float vr = xc * mr + xp * (1.0f - mr);
    float vg = xc * mg + xp * (1.0f - mg);
    f16 h, l;
    split_f16(vk, h, l); xkh[idx] = h; xkl[idx] = l;
    split_f16(vv, h, l); xvh[idx] = h; xvl[idx] = l;
    split_f16(vr, h, l); xrh[idx] = h; xrl[idx] = l;
    split_f16(vg, h, l); xgh[idx] = h; xgl[idx] = l;
}

// ---------------------------------------------------------------------------
// 2) Weight prep (batched over grid.z): transpose [K,N]->[N,K], fp16
// ---------------------------------------------------------------------------
struct WB { const float* W[5]; f16* O[5]; };

__global__ void wprep_b(WB wb) {
    const float* __restrict__ W = wb.W[blockIdx.z];
    f16* __restrict__ WT = wb.O[blockIdx.z];
    __shared__ float t[32][33];
    int n0 = blockIdx.x * 32, k0 = blockIdx.y * 32;
    int tx = threadIdx.x, ty = threadIdx.y;
    #pragma unroll
    for (int r = ty; r < 32; r += 8)
        t[r][tx] = W[(size_t)(k0 + r) * CC + n0 + tx];
    __syncthreads();
    #pragma unroll
    for (int r = ty; r < 32; r += 8)
        WT[(size_t)(n0 + r) * CC + k0 + tx] = __float2half_rn(t[tx][r]);
}

// ---------------------------------------------------------------------------
// 3) Batched fp16 split GEMM (grid.z selects problem)
// ---------------------------------------------------------------------------
struct GB {
    const f16* Ah[4]; const f16* Al[4]; const f16* Bp[4];
    float* Cp[4]; int act[4];
};

__global__ __launch_bounds__(256, 2) void tc_gemm_b(GB gb) {
    int z = blockIdx.z;
    const f16* __restrict__ Ah = gb.Ah[z];
    const f16* __restrict__ Al = gb.Al[z];
    const f16* __restrict__ B  = gb.Bp[z];
    float* __restrict__ C = gb.Cp[z];
    int act = gb.act[z];

    extern __shared__ char smem[];
    uint32_t sb = smem_u32(smem);

    int tid = threadIdx.x;
    int lane = tid & 31;
    int wm = (tid >> 5) & 3;
    int wn = tid >> 7;
    int mBase = blockIdx.y * BM;
    int nBase = blockIdx.x * BN;

    // closed-form cp.async mapping: 3 base pointers, 1 dst offset
    uint32_t dA = (uint32_t)((tid >> 2) * 80 + (tid & 3) * 16);
    const f16* pAh = Ah + (size_t)(mBase + (tid >> 2)) * CC + (tid & 3) * 8;
    const f16* pAl = Al + (size_t)(mBase + (tid >> 2)) * CC + (tid & 3) * 8;
    const f16* pB  = B  + (size_t)(nBase + (tid >> 2)) * CC + (tid & 3) * 8;

    float acc[2][8][4];
    #pragma unroll
    for (int i = 0; i < 2; i++)
        #pragma unroll
        for (int j = 0; j < 8; j++)
            #pragma unroll
            for (int q = 0; q < 4; q++) acc[i][j][q] = 0.0f;

    // prologue
    #pragma unroll
    for (int s = 0; s < NSTG - 1; s++) {
        uint32_t stb = sb + s * STAGE_B;
        int k0 = s * BKT;
        cpa16(stb + dA,                     pAh + k0);
        cpa16(stb + dA + 5120,              pAh + 64 * CC + k0);
        cpa16(stb + TILE_B + dA,            pAl + k0);
        cpa16(stb + TILE_B + dA + 5120,     pAl + 64 * CC + k0);
        cpa16(stb + 2 * TILE_B + dA,        pB + k0);
        cpa16(stb + 2 * TILE_B + dA + 5120, pB + 64 * CC + k0);
        cp_commit();
    }

    uint32_t aRow = (uint32_t)(wm * 32 + ((lane >> 3) & 1) * 8 + (lane & 7));
    uint32_t aCol = (uint32_t)((lane >> 4) * 16);
    uint32_t bRow = (uint32_t)(wn * 64 + (lane >> 4) * 8 + (lane & 7));
    uint32_t bCol = (uint32_t)(((lane >> 3) & 1) * 16);
    int ksSkew = wm & 1;

    int stgIdx = 0;
    for (int kt = 0; kt < KTILES; kt++) {
        cp_wait<1>();
        __syncthreads();

        int nt = kt + NSTG - 1;
        int pfs = stgIdx + (NSTG - 1); if (pfs >= NSTG) pfs -= NSTG;
        if (nt < KTILES) {
            uint32_t stb = sb + pfs * STAGE_B;
            int k0 = nt * BKT;
            cpa16(stb + dA,                     pAh + k0);
            cpa16(stb + dA + 5120,              pAh + 64 * CC + k0);
            cpa16(stb + TILE_B + dA,            pAl + k0);
            cpa16(stb + TILE_B + dA + 5120,     pAl + 64 * CC + k0);
            cpa16(stb + 2 * TILE_B + dA,        pB + k0);
            cpa16(stb + 2 * TILE_B + dA + 5120, pB + 64 * CC + k0);
        }
        cp_commit();

        uint32_t stg = sb + stgIdx * STAGE_B;
        if (++stgIdx == NSTG) stgIdx = 0;

        #pragma unroll
        for (int kss = 0; kss < 2; kss++) {
            int ks = kss ^ ksSkew;   // de-correlate ldsm phases across warps
            uint32_t a_h[2][4], a_l[2][4];
            #pragma unroll
            for (int mi = 0; mi < 2; mi++) {
                uint32_t ra = (aRow + mi * 16) * 80 + aCol + ks * 32;
                ldsm4(a_h[mi], stg + 0 * TILE_B + ra);
                ldsm4(a_l[mi], stg + 1 * TILE_B + ra);
            }
            #pragma unroll
            for (int bp = 0; bp < 2; bp++) {
                uint32_t b0[4], b1[4];
                {
                    uint32_t rb0 = (bRow + (2*bp + 0) * 16) * 80 + bCol + ks * 32;
                    uint32_t rb1 = (bRow + (2*bp + 1) * 16) * 80 + bCol + ks * 32;
                    ldsm4(b0, stg + 2 * TILE_B + rb0);
                    ldsm4(b1, stg + 2 * TILE_B + rb1);
                }
                #pragma unroll
                for (int mi = 0; mi < 2; mi++) {
                    mma_f16(acc[mi][4*bp + 0], a_h[mi], b0[0], b0[1]);
                    mma_f16(acc[mi][4*bp + 1], a_h[mi], b0[2], b0[3]);
                    mma_f16(acc[mi][4*bp + 2], a_h[mi], b1[0], b1[1]);
                    mma_f16(acc[mi][4*bp + 3], a_h[mi], b1[2], b1[3]);
                }
                #pragma unroll
                for (int mi = 0; mi < 2; mi++) {
                    mma_f16(acc[mi][4*bp + 0], a_l[mi], b0[0], b0[1]);
                    mma_f16(acc[mi][4*bp + 1], a_l[mi], b0[2], b0[3]);
                    mma_f16(acc[mi][4*bp + 2], a_l[mi], b1[0], b1[1]);
                    mma_f16(acc[mi][4*bp + 3], a_l[mi], b1[2], b1[3]);
                }
            }
        }
    }

    int mrow = mBase + wm * 32 + (lane >> 2);
    int ncolbase = nBase + wn * 64 + (lane & 3) * 2;
    #pragma unroll
    for (int mi = 0; mi < 2; mi++) {
        #pragma unroll
        for (int bp = 0; bp < 2; bp++) {
            #pragma unroll
            for (int s = 0; s < 4; s++) {
                int njp = 2*bp + (s >> 1);
                int q = s & 1;
                int ni_col = njp * 16 + q * 8;
                float v0 = acc[mi][4*bp + s][0], v1 = acc[mi][4*bp + s][1];
                float v2 = acc[mi][4*bp + s][2], v3 = acc[mi][4*bp + s][3];
                if (act) {
                    v0 = v0 / (1.0f + expf(-v0));
                    v1 = v1 / (1.0f + expf(-v1));
                    v2 = v2 / (1.0f + expf(-v2));
                    v3 = v3 / (1.0f + expf(-v3));
                }
                float* p0 = C + (size_t)(mrow + mi * 16) * CC + ncolbase + ni_col;
                float* p1 = p0 + 8 * CC;
                *(float2*)p0 = make_float2(v0, v1);
                *(float2*)p1 = make_float2(v2, v3);
            }
        }
    }
}

// ---------------------------------------------------------------------------
// 4) Chunked RWKV scan
// ---------------------------------------------------------------------------
__global__ __launch_bounds__(HS) void scanA_kernel(
        const float* __restrict__ k, const float* __restrict__ v,
        const float* __restrict__ td, float* __restrict__ Sc) {
    int bh = blockIdx.x;
    int chunk = blockIdx.y;
    int b = bh >> 5, h = bh & 31;
    int j = threadIdx.x;

    float w = expf(-expf(td[h]));
    float S[HS];
    #pragma unroll
    for (int a = 0; a < HS; a++) S[a] = 0.0f;

    __shared__ float sk[2][HS], sv[2][HS];
    size_t base = (size_t)b * TTOT * CC + (size_t)h * HS;
    int t0 = chunk * TCH;

    sk[0][j] = k[base + (size_t)t0 * CC + j];
    sv[0][j] = v[base + (size_t)t0 * CC + j];
    __syncthreads();

    for (int i = 0; i < TCH; i++) {
        int cb = i & 1;
        float kn = 0.0f, vn = 0.0f;
        if (i + 1 < TCH) {
            size_t o2 = base + (size_t)(t0 + i + 1) * CC;
            kn = k[o2 + j]; vn = v[o2 + j];
        }
        float vj = sv[cb][j];
        #pragma unroll
        for (int a = 0; a < HS; a++)
            S[a] = fmaf(w, S[a], sk[cb][a] * vj);
        sk[cb ^ 1][j] = kn;
        sv[cb ^ 1][j] = vn;
        __syncthreads();
    }
    size_t o = ((size_t)(chunk * 128 + bh) * HS) * HS + j;
    #pragma unroll
    for (int a = 0; a < HS; a++)
        Sc[o + (size_t)a * HS] = S[a];
}

__global__ __launch_bounds__(HS) void scanB_kernel(
        const float* __restrict__ s0, const float* __restrict__ Sc,
        const float* __restrict__ td, float* __restrict__ S0c) {
    int bh = blockIdx.x;
    int h = bh & 31;
    int j = threadIdx.x;
    float wT = expf(-expf(td[h]) * (float)TCH);

    float s[HS];
    #pragma unroll
    for (int a = 0; a < HS; a++)
        s[a] = s0[((size_t)bh * HS + a) * HS + j];

    for (int c = 0; c < NCHUNK; c++) {
        size_t o = ((size_t)(c * 128 + bh) * HS) * HS + j;
        #pragma unroll
        for (int a = 0; a < HS; a++) {
            S0c[o + (size_t)a * HS] = s[a];
            s[a] = fmaf(wT, s[a], Sc[o + (size_t)a * HS]);
        }
    }
}

// Phase C fused with groupnorm + gate: emits fp16 hi/lo y planes directly.
__global__ __launch_bounds__(HS) void scanC_kernel(
        const float* __restrict__ r, const float* __restrict__ k,
        const float* __restrict__ v, const float* __restrict__ g,
        const float* __restrict__ td, const float* __restrict__ tf,
        const float* __restrict__ S0c,
        const float* __restrict__ gamma, const float* __restrict__ beta,
        f16* __restrict__ yh, f16* __restrict__ yl) {
    int bh = blockIdx.x;
    int chunk = blockIdx.y;
    int b = bh >> 5, h = bh & 31;
    int j = threadIdx.x;
    int warp = j >> 5, lane = j & 31;

    float w = expf(-expf(td[h]));
    float u = tf[h];
    float gam = gamma[h * HS + j];
    float bet = beta[h * HS + j];

    float s[HS];
    size_t so = ((size_t)(chunk * 128 + bh) * HS) * HS + j;
    #pragma unroll
    for (int a = 0; a < HS; a++)
        s[a] = S0c[so + (size_t)a * HS];

    __shared__ float sr[2][HS], sk[2][HS], sv[2][HS];
    __shared__ float redK[2], redM[2], redV[2];
    size_t base = (size_t)b * TTOT * CC + (size_t)h * HS;
    int t0 = chunk * TCH;

    {
        size_t o1 = base + (size_t)t0 * CC;
        sr[0][j] = r[o1 + j]; sk[0][j] = k[o1 + j]; sv[0][j] = v[o1 + j];
    }
    __syncthreads();

    for (int i = 0; i < TCH; i++) {
        int cb = i & 1;
        size_t ocur = base + (size_t)(t0 + i) * CC;
        float gcur = g[ocur + j];
        float rn = 0.0f, kn = 0.0f, vn = 0.0f;
        if (i + 1 < TCH) {
            size_t o2 = ocur + CC;
            rn = r[o2 + j]; kn = k[o2 + j]; vn = v[o2 + j];
        }

        // --- phase 1: r.k via block reduce
        float p = sr[cb][j] * sk[cb][j];
        #pragma unroll
        for (int o = 16; o; o >>= 1) p += __shfl_xor_sync(0xffffffffu, p, o);
        if (lane == 0) redK[warp] = p;
        __syncthreads();
        float kr = redK[0] + redK[1];

        // --- phase 2: output + state update, then mean/var partials
        float vj = sv[cb][j];
        float oacc = 0.0f;
        #pragma unroll
        for (int a = 0; a < HS; a++) {
            float ka = sk[cb][a];
            oacc = fmaf(sr[cb][a], s[a], oacc);
            s[a] = fmaf(w, s[a], ka * vj);
        }
        oacc = fmaf(u * kr, vj, oacc);
        float ov = oacc * 0.125f;
        float s1 = ov, s2 = ov * ov;
        #pragma unroll
        for (int o = 16; o; o >>= 1) {
            s1 += __shfl_xor_sync(0xffffffffu, s1, o);
            s2 += __shfl_xor_sync(0xffffffffu, s2, o);
        }
        if (lane == 0) { redM[warp] = s1; redV[warp] = s2; }
        __syncthreads();

        // --- phase 3: normalize, gate, store, rotate buffers
        float mu  = (redM[0] + redM[1]) * (1.0f / 64.0f);
        float var = (redV[0] + redV[1]) * (1.0f / 64.0f) - mu * mu;
        float inv = rsqrtf(var + 1e-5f);
        float y = ((ov - mu) * inv * gam + bet) * gcur;
        f16 hh, ll;
        split_f16(y, hh, ll);
        yh[ocur + j] = hh;
        yl[ocur + j] = ll;

        sr[cb ^ 1][j] = rn; sk[cb ^ 1][j] = kn; sv[cb ^ 1][j] = vn;
        __syncthreads();
    }
}

// ---------------------------------------------------------------------------
// Launcher
// ---------------------------------------------------------------------------
extern "C" void kernel_launch(void* const* d_in, const int* in_sizes, int n_in,
                              void* d_out, int out_size) {
    const float* x     = (const float*)d_in[0];
    const float* Wr    = (const float*)d_in[1];
    const float* Wk    = (const float*)d_in[2];
    const float* Wv    = (const float*)d_in[3];
    const float* Wg    = (const float*)d_in[4];
    const float* Wo    = (const float*)d_in[5];
    const float* gamma = (const float*)d_in[6];
    const float* beta  = (const float*)d_in[7];
    const float* tmk   = (const float*)d_in[8];
    const float* tmv   = (const float*)d_in[9];
    const float* tmr   = (const float*)d_in[10];
    const float* tmg   = (const float*)d_in[11];
    const float* td    = (const float*)d_in[12];
    const float* tf    = (const float*)d_in[13];
    const float* s0    = (const float*)d_in[14];
    float* out = (float*)d_out;

    static bool attr_done = false;
    if (!attr_done) {
        cudaFuncSetAttribute(tc_gemm_b, cudaFuncAttributeMaxDynamicSharedMemorySize, SMEM_B);
        attr_done = true;
    }

    f16 *xrh,*xrl,*xkh,*xkl,*xvh,*xvl,*xgh,*xgl,*yh,*yl;
    f16 *wrt,*wkt,*wvt,*wgt,*wot;
    float *rb,*kb,*vb,*gb,*Sc,*S0c;
    cudaGetSymbolAddress((void**)&xrh, g_xr_h); cudaGetSymbolAddress((void**)&xrl, g_xr_l);
    cudaGetSymbolAddress((void**)&xkh, g_xk_h); cudaGetSymbolAddress((void**)&xkl, g_xk_l);
    cudaGetSymbolAddress((void**)&xvh, g_xv_h); cudaGetSymbolAddress((void**)&xvl, g_xv_l);
    cudaGetSymbolAddress((void**)&xgh, g_xg_h); cudaGetSymbolAddress((void**)&xgl, g_xg_l);
    cudaGetSymbolAddress((void**)&yh,  g_y_h);  cudaGetSymbolAddress((void**)&yl,  g_y_l);
    cudaGetSymbolAddress((void**)&rb, g_r); cudaGetSymbolAddress((void**)&kb, g_k);
    cudaGetSymbolAddress((void**)&vb, g_v); cudaGetSymbolAddress((void**)&gb, g_g);
    cudaGetSymbolAddress((void**)&Sc, g_Sc); cudaGetSymbolAddress((void**)&S0c, g_S0c);
    cudaGetSymbolAddress((void**)&wrt, g_WrT);
    cudaGetSymbolAddress((void**)&wkt, g_WkT);
    cudaGetSymbolAddress((void**)&wvt, g_WvT);
    cudaGetSymbolAddress((void**)&wgt, g_WgT);
    cudaGetSymbolAddress((void**)&wot, g_WoT);

    // 1) all weight transposes in one launch
    WB wb;
    wb.W[0] = Wr; wb.W[1] = Wk; wb.W[2] = Wv; wb.W[3] = Wg; wb.W[4] = Wo;
    wb.O[0] = wrt; wb.O[1] = wkt; wb.O[2] = wvt; wb.O[3] = wgt; wb.O[4] = wot;
    wprep_b<<<dim3(CC/32, CC/32, 5), dim3(32, 8)>>>(wb);

    // 2) mix
    int mixBlocks = (int)((ELEMS + 255) / 256);
    mix_kernel<<<mixBlocks, 256>>>(x, tmk, tmv, tmr, tmg,
                                   xkh, xkl, xvh, xvl, xrh, xrl, xgh, xgl);

    // 3) 4 projection GEMMs in one launch
    GB g4;
    g4.Ah[0] = xrh; g4.Al[0] = xrl; g4.Bp[0] = wrt; g4.Cp[0] = rb; g4.act[0] = 0;
    g4.Ah[1] = xkh; g4.Al[1] = xkl; g4.Bp[1] = wkt; g4.Cp[1] = kb; g4.act[1] = 0;
    g4.Ah[2] = xvh; g4.Al[2] = xvl; g4.Bp[2] = wvt; g4.Cp[2] = vb; g4.act[2] = 0;
    g4.Ah[3] = xgh; g4.Al[3] = xgl; g4.Bp[3] = wgt; g4.Cp[3] = gb; g4.act[3] = 1;
    tc_gemm_b<<<dim3(CC/BN, ROWS/BM, 4), 256, SMEM_B>>>(g4);

    // 4) scan (C fused with groupnorm+gate)
    dim3 sg(128, NCHUNK);
    scanA_kernel<<<sg, HS>>>(kb, vb, td, Sc);
    scanB_kernel<<<128, HS>>>(s0, Sc, td, S0c);
    scanC_kernel<<<sg, HS>>>(rb, kb, vb, gb, td, tf, S0c, gamma, beta, yh, yl);

    // 5) output projection
    GB g1;
    g1.Ah[0] = yh; g1.Al[0] = yl; g1.Bp[0] = wot; g1.Cp[0] = out; g1.act[0] = 0;
    g1.Ah[1] = yh; g1.Al[1] = yl; g1.Bp[1] = wot; g1.Cp[1] = out; g1.act[1] = 0;
    g1.Ah[2] = yh; g1.Al[2] = yl; g1.Bp[2] = wot; g1.Cp[2] = out; g1.act[2] = 0;
    g1.Ah[3] = yh; g1.Al[3] = yl; g1.Bp[3] = wot; g1.Cp[3] = out; g1.act[3] = 0;
    tc_gemm_b<<<dim3(CC/BN, ROWS/BM, 1), 256, SMEM_B>>>(g1);
}